// round 4
// baseline (speedup 1.0000x reference)
#include <cuda_runtime.h>
#include <cuda_bf16.h>

// ---------------------------------------------------------------------------
// ModelSimple: conv4d(1->5,k7)+ReLU -> conv4d(5->10,k7)+ReLU -> Linear -> sigmoid
// R4: ot-full per thread (210 FFMA2 per x-row), GMEM pre-duplicated weights
//     (contiguous float4 staging), khw-group SMEM reduction.
// ---------------------------------------------------------------------------

#define ULL unsigned long long

__device__ __forceinline__ ULL pack2(float a, float b) {
    ULL r;
    asm("mov.b64 %0, {%1, %2};" : "=l"(r) : "f"(a), "f"(b));
    return r;
}
__device__ __forceinline__ ULL fma2(ULL a, ULL b, ULL c) {
    ULL d;
    asm("fma.rn.f32x2 %0, %1, %2, %3;" : "=l"(d) : "l"(a), "l"(b), "l"(c));
    return d;
}
__device__ __forceinline__ ULL add2(ULL a, ULL b) {
    ULL d;
    asm("add.rn.f32x2 %0, %1, %2;" : "=l"(d) : "l"(a), "l"(b));
    return d;
}
__device__ __forceinline__ float2 unpack2(ULL v) {
    float2 f;
    asm("mov.b64 {%0, %1}, %2;" : "=f"(f.x), "=f"(f.y) : "l"(v));
    return f;
}

// Scratch (device globals: allocation-free per harness rules)
__device__ float g_h1[128 * 5 * 20736];   // [b][oc][oh*1728 + ow*144 + od*12 + ot]
__device__ float g_h2[128 * 10 * 1296];   // [b][oc][oh*216 + ow*36 + od*6 + ot]
__device__ ULL   g_w1d[12006];            // w1 dup pairs, [oc][ki=khw*7+kd][kt]
__device__ ULL   g_w2d[10 * 12006];       // w2 dup pairs, slot (ocg*5+ic): [ocl][2401]

// ---------------------------------------------------------------------------
// Weight duplication prep kernels (run each launch; trivial cost)
// ---------------------------------------------------------------------------
__global__ void dup_w1_kernel(const float* __restrict__ w1) {
    const int i = blockIdx.x * 256 + threadIdx.x;
    if (i < 12006) {
        const float v = (i < 12005) ? w1[i] : 0.0f;
        g_w1d[i] = pack2(v, v);
    }
}
__global__ void dup_w2_kernel(const float* __restrict__ w2) {
    const int i = blockIdx.x * 256 + threadIdx.x;
    if (i < 10 * 12006) {
        const int slot = i / 12006;           // slot = ocg*5 + ic
        const int j    = i - slot * 12006;    // [ocl][2401]
        const int ocg  = slot / 5;
        const int ic   = slot - ocg * 5;
        float v = 0.0f;
        if (j < 12005) {
            const int ocl = j / 2401;
            const int r   = j - ocl * 2401;
            v = w2[(size_t)((ocg * 5 + ocl) * 5 + ic) * 2401 + r];
        }
        g_w2d[i] = pack2(v, v);
    }
}

// ---------------------------------------------------------------------------
// conv1: grid = 128*12*2 (b, oh, ow-half); 432 thr = 6 khw-groups x 72 (ow6,od12)
// Each thread: full ot (12) for all 5 oc -> acc[5][6] f32x2 pairs.
// SMEM: x slab [7,12,18,18]=27216 f (108,864B) + w dup 12006 ULL (96,048B)
// ---------------------------------------------------------------------------
__global__ __launch_bounds__(432, 1)
void conv1_kernel(const float* __restrict__ x,
                  const float* __restrict__ b1) {
    extern __shared__ float sm[];
    float* sx = sm;                          // 27216 floats
    ULL*   swU = (ULL*)(sm + 27216);         // 12006 ULL dup pairs; reused for reduction

    const int bx  = blockIdx.x;
    const int b   = bx / 24;
    const int oh  = (bx % 24) >> 1;
    const int owb = (bx & 1) * 6;
    const int tid = threadIdx.x;

    // Stage x slab: per kh, 3888 contiguous floats (972 float4)
    {
        const float* src = x + (size_t)b * 104976 + oh * 5832 + owb * 324;
        float4* d4 = (float4*)sx;
        for (int i = tid; i < 6804; i += 432) {
            const int kh = i / 972;
            const int j  = i - kh * 972;
            d4[i] = ((const float4*)(src + kh * 5832))[j];
        }
        // Weights: contiguous float4 copy of pre-duplicated pairs
        const float4* ws = (const float4*)g_w1d;
        float4* wd = (float4*)swU;
        for (int i = tid; i < 6003; i += 432) wd[i] = ws[i];
    }
    __syncthreads();

    const int g  = tid / 72;                 // khw group 0..5
    const int t  = tid - g * 72;
    const int ow = t / 12;                   // 0..5 (local)
    const int od = t - ow * 12;              // 0..11

    ULL acc[5][6];
    #pragma unroll
    for (int oc = 0; oc < 5; oc++)
        #pragma unroll
        for (int p = 0; p < 6; p++) acc[oc][p] = 0ULL;

    const int k0 = (g == 0) ? 0 : (9 + (g - 1) * 8);
    const int k1 = k0 + ((g == 0) ? 9 : 8);

    #pragma unroll 1
    for (int khw = k0; khw < k1; khw++) {
        const int kh = khw / 7;
        const int kw = khw - kh * 7;
        const float* base = sx + kh * 3888 + (ow + kw) * 324 + od * 18;
        #pragma unroll 1
        for (int kd = 0; kd < 7; kd++) {
            const ULL* rowU = (const ULL*)(base + kd * 18);
            // 9 even pairs straight from LDS.64
            ULL xe[9];
            #pragma unroll
            for (int j = 0; j < 9; j++) xe[j] = rowU[j];
            // 8 odd pairs (hi of xe[j], lo of xe[j+1])
            ULL xo[8];
            #pragma unroll
            for (int j = 0; j < 8; j++) {
                const float2 a = unpack2(xe[j]);
                const float2 c = unpack2(xe[j + 1]);
                xo[j] = pack2(a.y, c.x);
            }

            const ULL* wp = swU + (khw * 7 + kd) * 7;
            #pragma unroll 1
            for (int oc = 0; oc < 5; oc++) {
                ULL w0 = wp[0], w1_ = wp[1], w2_ = wp[2], w3_ = wp[3];
                ULL w4 = wp[4], w5 = wp[5], w6 = wp[6];
                #pragma unroll
                for (int p = 0; p < 6; p++) {
                    acc[oc][p] = fma2(xe[p + 0], w0, acc[oc][p]);
                    acc[oc][p] = fma2(xo[p + 0], w1_, acc[oc][p]);
                    acc[oc][p] = fma2(xe[p + 1], w2_, acc[oc][p]);
                    acc[oc][p] = fma2(xo[p + 1], w3_, acc[oc][p]);
                    acc[oc][p] = fma2(xe[p + 2], w4, acc[oc][p]);
                    acc[oc][p] = fma2(xo[p + 2], w5, acc[oc][p]);
                    acc[oc][p] = fma2(xe[p + 3], w6, acc[oc][p]);
                }
                wp += 2401;
            }
        }
    }

    // 6-way khw reduction through SMEM (reuse weight region: 5*72*30 ULL = 86,400B)
    __syncthreads();
    ULL* red = swU;
    if (g != 0) {
        #pragma unroll
        for (int oc = 0; oc < 5; oc++)
            #pragma unroll
            for (int p = 0; p < 6; p++)
                red[((g - 1) * 72 + t) * 30 + oc * 6 + p] = acc[oc][p];
    }
    __syncthreads();

    if (g == 0) {
        const int sbase = oh * 1728 + (owb + ow) * 144 + od * 12;
        #pragma unroll
        for (int oc = 0; oc < 5; oc++) {
            const float bb = __ldg(b1 + oc);
            float* dst = g_h1 + (size_t)(b * 5 + oc) * 20736 + sbase;
            #pragma unroll
            for (int p = 0; p < 6; p++) {
                ULL a = acc[oc][p];
                #pragma unroll
                for (int q = 0; q < 5; q++)
                    a = add2(a, red[(q * 72 + t) * 30 + oc * 6 + p]);
                const float2 f = unpack2(a);
                float2 o;
                o.x = fmaxf(f.x + bb, 0.0f);
                o.y = fmaxf(f.y + bb, 0.0f);
                *(float2*)(dst + 2 * p) = o;
            }
        }
    }
}

// ---------------------------------------------------------------------------
// conv2: grid = 128*2 (b, oc-group); 432 thr = 2 khw-groups x 216 (oh,ow,od)
// Each thread: full ot (6) for 5 oc -> acc[5... wait 10? ocg gives 5 oc here? No:
// each CTA handles 5 oc (its ocg); thread accumulates acc[5][3].
// Loop ic: SMEM h1 slab 20736 f (82,944B) + w dup 12006 ULL (96,048B)
// ---------------------------------------------------------------------------
__global__ __launch_bounds__(432, 1)
void conv2_kernel(const float* __restrict__ b2) {
    extern __shared__ float sm[];
    float* sx = sm;                          // 20736 floats
    ULL*   swU = (ULL*)(sm + 20736);         // 12006 ULL; reused for reduction

    const int bx  = blockIdx.x;
    const int b   = bx >> 1;
    const int ocg = bx & 1;
    const int ocb = ocg * 5;
    const int tid = threadIdx.x;
    const int g   = tid / 216;               // khw group 0,1
    const int t   = tid - g * 216;
    const int oh  = t / 36;
    const int ow  = (t % 36) / 6;
    const int od  = t % 6;

    ULL acc[5][3];
    #pragma unroll
    for (int oc = 0; oc < 5; oc++)
        #pragma unroll
        for (int p = 0; p < 3; p++) acc[oc][p] = 0ULL;

    const int k0 = g ? 25 : 0;
    const int k1 = g ? 49 : 25;

    for (int ic = 0; ic < 5; ic++) {
        __syncthreads();   // protect previous iteration's SMEM reads
        {
            const float4* s4 = (const float4*)(g_h1 + (size_t)(b * 5 + ic) * 20736);
            float4* d4 = (float4*)sx;
            for (int i = tid; i < 5184; i += 432) d4[i] = s4[i];
            const float4* ws = (const float4*)(g_w2d + (size_t)(ocg * 5 + ic) * 12006);
            float4* wd = (float4*)swU;
            for (int i = tid; i < 6003; i += 432) wd[i] = ws[i];
        }
        __syncthreads();

        #pragma unroll 1
        for (int khw = k0; khw < k1; khw++) {
            const int kh = khw / 7;
            const int kw = khw - kh * 7;
            const float* base = sx + ((oh + kh) * 12 + ow + kw) * 144 + od * 12;
            #pragma unroll 1
            for (int kd = 0; kd < 7; kd++) {
                const ULL* rowU = (const ULL*)(base + kd * 12);
                ULL xe[6];
                #pragma unroll
                for (int j = 0; j < 6; j++) xe[j] = rowU[j];
                ULL xo[5];
                #pragma unroll
                for (int j = 0; j < 5; j++) {
                    const float2 a = unpack2(xe[j]);
                    const float2 c = unpack2(xe[j + 1]);
                    xo[j] = pack2(a.y, c.x);
                }

                const ULL* wp = swU + (khw * 7 + kd) * 7;
                #pragma unroll 1
                for (int oc = 0; oc < 5; oc++) {
                    ULL w0 = wp[0], w1_ = wp[1], w2_ = wp[2], w3_ = wp[3];
                    ULL w4 = wp[4], w5 = wp[5], w6 = wp[6];
                    #pragma unroll
                    for (int p = 0; p < 3; p++) {
                        acc[oc][p] = fma2(xe[p + 0], w0, acc[oc][p]);
                        acc[oc][p] = fma2(xo[p + 0], w1_, acc[oc][p]);
                        acc[oc][p] = fma2(xe[p + 1], w2_, acc[oc][p]);
                        acc[oc][p] = fma2(xo[p + 1], w3_, acc[oc][p]);
                        acc[oc][p] = fma2(xe[p + 2], w4, acc[oc][p]);
                        acc[oc][p] = fma2(xo[p + 2], w5, acc[oc][p]);
                        acc[oc][p] = fma2(xe[p + 3], w6, acc[oc][p]);
                    }
                    wp += 2401;
                }
            }
        }
    }

    // 2-way khw reduction through SMEM (216*30 ULL = 51,840B into w region)
    __syncthreads();
    ULL* red = swU;
    if (g == 1) {
        #pragma unroll
        for (int oc = 0; oc < 5; oc++)
            #pragma unroll
            for (int p = 0; p < 3; p++)
                red[t * 30 + oc * 3 + p] = acc[oc][p];
    }
    __syncthreads();

    if (g == 0) {
        const int sp = oh * 216 + ow * 36 + od * 6;
        #pragma unroll
        for (int oc = 0; oc < 5; oc++) {
            const float bb = __ldg(b2 + ocb + oc);
            float* dst = g_h2 + (size_t)(b * 10 + ocb + oc) * 1296 + sp;
            #pragma unroll
            for (int p = 0; p < 3; p++) {
                const ULL a = add2(acc[oc][p], red[t * 30 + oc * 3 + p]);
                const float2 f = unpack2(a);
                float2 o;
                o.x = fmaxf(f.x + bb, 0.0f);
                o.y = fmaxf(f.y + bb, 0.0f);
                *(float2*)(dst + 2 * p) = o;
            }
        }
    }
}

// ---------------------------------------------------------------------------
// head: Linear(12960 -> 1) + sigmoid. grid = 128 (b), 128 threads.
// ---------------------------------------------------------------------------
__global__ __launch_bounds__(128, 8)
void head_kernel(const float* __restrict__ wl,
                 const float* __restrict__ bl,
                 float* __restrict__ out) {
    const int b   = blockIdx.x;
    const int tid = threadIdx.x;
    const float* h = g_h2 + (size_t)b * 12960;

    float sum = 0.0f;
    for (int i = tid; i < 12960; i += 128)
        sum += h[i] * wl[i];

    #pragma unroll
    for (int o = 16; o > 0; o >>= 1)
        sum += __shfl_xor_sync(0xffffffffu, sum, o);

    __shared__ float red[4];
    if ((tid & 31) == 0) red[tid >> 5] = sum;
    __syncthreads();
    if (tid == 0) {
        float z = red[0] + red[1] + red[2] + red[3] + bl[0];
        out[b] = 1.0f / (1.0f + expf(-z));
    }
}

// ---------------------------------------------------------------------------
extern "C" void kernel_launch(void* const* d_in, const int* in_sizes, int n_in,
                              void* d_out, int out_size) {
    const float* x  = (const float*)d_in[0];
    const float* w1 = (const float*)d_in[1];
    const float* b1 = (const float*)d_in[2];
    const float* w2 = (const float*)d_in[3];
    const float* b2 = (const float*)d_in[4];
    const float* wl = (const float*)d_in[5];
    const float* bl = (const float*)d_in[6];

    const int smem1 = 108864 + 96048;  // 204,912 B
    const int smem2 = 82944 + 96048;   // 178,992 B
    cudaFuncSetAttribute(conv1_kernel, cudaFuncAttributeMaxDynamicSharedMemorySize, smem1);
    cudaFuncSetAttribute(conv2_kernel, cudaFuncAttributeMaxDynamicSharedMemorySize, smem2);

    dup_w1_kernel<<<(12006 + 255) / 256, 256>>>(w1);
    dup_w2_kernel<<<(10 * 12006 + 255) / 256, 256>>>(w2);
    conv1_kernel<<<128 * 24, 432, smem1>>>(x, b1);
    conv2_kernel<<<128 * 2, 432, smem2>>>(b2);
    head_kernel<<<128, 128>>>(wl, bl, (float*)d_out);
}

// round 5
// speedup vs baseline: 2.0031x; 2.0031x over previous
#include <cuda_runtime.h>
#include <cuda_bf16.h>

// ---------------------------------------------------------------------------
// ModelSimple: conv4d(1->5,k7)+ReLU -> conv4d(5->10,k7)+ReLU -> Linear -> sigmoid
// R5: R2 inner loop (register-dup weights, acc[5][3], full unroll) with 864
//     threads/CTA (27 warps) via deeper khw-splits; SMEM reduction reuses the
//     dead x-slab region. Fix for R2's eligible-warp starvation (issue=53.7%).
// ---------------------------------------------------------------------------

#define ULL unsigned long long

__device__ __forceinline__ ULL pack2(float a, float b) {
    ULL r;
    asm("mov.b64 %0, {%1, %2};" : "=l"(r) : "f"(a), "f"(b));
    return r;
}
__device__ __forceinline__ ULL fma2(ULL a, ULL b, ULL c) {
    ULL d;
    asm("fma.rn.f32x2 %0, %1, %2, %3;" : "=l"(d) : "l"(a), "l"(b), "l"(c));
    return d;
}
__device__ __forceinline__ ULL add2(ULL a, ULL b) {
    ULL d;
    asm("add.rn.f32x2 %0, %1, %2;" : "=l"(d) : "l"(a), "l"(b));
    return d;
}
__device__ __forceinline__ float2 unpack2(ULL v) {
    float2 f;
    asm("mov.b64 {%0, %1}, %2;" : "=f"(f.x), "=f"(f.y) : "l"(v));
    return f;
}

// Scratch (device globals: allocation-free per harness rules)
__device__ float g_h1[128 * 5 * 20736];   // [b][oc][oh*1728 + ow*144 + od*12 + ot]
__device__ float g_h2[128 * 10 * 1296];   // [b][oc][oh*216 + ow*36 + od*6 + ot]

// ---------------------------------------------------------------------------
// conv1: grid = 128*12 (b, oh); 864 thr = 3 khw-groups x 288 (ow12, od12, ot2)
// SMEM: x slab [7,18,18,18]=40824 f (163,296B) + w1 padded [5][343][8]=13720 f
//       = 218,176 B. Reduction reuses the x-slab region after compute.
// ---------------------------------------------------------------------------
__global__ __launch_bounds__(864, 1)
void conv1_kernel(const float* __restrict__ x,
                  const float* __restrict__ w1,
                  const float* __restrict__ b1) {
    extern __shared__ float sm[];
    float* sx = sm;           // 40824 floats (reused as reduction scratch)
    float* sw = sm + 40824;   // 13720 floats (8-padded weights)

    const int bx  = blockIdx.x;
    const int b   = bx / 12;
    const int oh  = bx % 12;
    const int tid = threadIdx.x;

    // Stage x slab (one contiguous chunk) + padded weights
    {
        const float4* s4 = (const float4*)(x + (size_t)b * 104976 + oh * 5832);
        float4* d4 = (float4*)sx;
        for (int i = tid; i < 10206; i += 864) d4[i] = s4[i];
        for (int i = tid; i < 12005; i += 864) {
            const int oc = i / 2401;
            const int r  = i - oc * 2401;
            const int ki = r / 7;
            const int kt = r - ki * 7;
            sw[(oc * 343 + ki) * 8 + kt] = w1[i];
        }
    }
    __syncthreads();

    const int g   = tid / 288;           // khw group 0..2 (17/16/16 khw)
    const int t   = tid - g * 288;
    const int ow  = t / 24;
    const int r   = t % 24;
    const int od  = r >> 1;
    const int ot0 = (r & 1) * 6;

    ULL acc[5][3];
    #pragma unroll
    for (int oc = 0; oc < 5; oc++)
        #pragma unroll
        for (int p = 0; p < 3; p++) acc[oc][p] = 0ULL;

    const int colbase = od * 18 + ot0;
    const int k0 = (g == 0) ? 0 : (17 + (g - 1) * 16);
    const int k1 = k0 + ((g == 0) ? 17 : 16);

    #pragma unroll 1
    for (int khw = k0; khw < k1; khw++) {
        const int kh = khw / 7;
        const int kw = khw - kh * 7;
        const float* rowc = sx + kh * 5832 + (ow + kw) * 324 + colbase;
        #pragma unroll 1
        for (int kd = 0; kd < 7; kd++) {
            const float* row = rowc + kd * 18;
            float2 v0 = *(const float2*)(row + 0);
            float2 v1 = *(const float2*)(row + 2);
            float2 v2 = *(const float2*)(row + 4);
            float2 v3 = *(const float2*)(row + 6);
            float2 v4 = *(const float2*)(row + 8);
            float2 v5 = *(const float2*)(row + 10);
            ULL xp[11];
            xp[0]  = pack2(v0.x, v0.y);
            xp[2]  = pack2(v1.x, v1.y);
            xp[4]  = pack2(v2.x, v2.y);
            xp[6]  = pack2(v3.x, v3.y);
            xp[8]  = pack2(v4.x, v4.y);
            xp[10] = pack2(v5.x, v5.y);
            xp[1]  = pack2(v0.y, v1.x);
            xp[3]  = pack2(v1.y, v2.x);
            xp[5]  = pack2(v2.y, v3.x);
            xp[7]  = pack2(v3.y, v4.x);
            xp[9]  = pack2(v4.y, v5.x);

            const int kib = khw * 7 + kd;
            #pragma unroll
            for (int oc = 0; oc < 5; oc++) {
                const float* wb = sw + (oc * 343 + kib) * 8;
                const float2 wA = *(const float2*)(wb + 0);
                const float2 wB = *(const float2*)(wb + 2);
                const float2 wC = *(const float2*)(wb + 4);
                const float2 wD = *(const float2*)(wb + 6);
                const float wk[7] = {wA.x, wA.y, wB.x, wB.y, wC.x, wC.y, wD.x};
                #pragma unroll
                for (int kt = 0; kt < 7; kt++) {
                    const ULL wp = pack2(wk[kt], wk[kt]);
                    acc[oc][0] = fma2(xp[kt + 0], wp, acc[oc][0]);
                    acc[oc][1] = fma2(xp[kt + 2], wp, acc[oc][1]);
                    acc[oc][2] = fma2(xp[kt + 4], wp, acc[oc][2]);
                }
            }
        }
    }

    // 3-way khw reduction through SMEM (reuse x region: 2*288*15 ULL = 69,120B)
    __syncthreads();
    ULL* red = (ULL*)sm;
    if (g != 0) {
        #pragma unroll
        for (int oc = 0; oc < 5; oc++)
            #pragma unroll
            for (int p = 0; p < 3; p++)
                red[((g - 1) * 288 + t) * 15 + oc * 3 + p] = acc[oc][p];
    }
    __syncthreads();

    if (g == 0) {
        const int sbase = oh * 1728 + ow * 144 + od * 12 + ot0;
        #pragma unroll
        for (int oc = 0; oc < 5; oc++) {
            const float bb = __ldg(b1 + oc);
            float* dst = g_h1 + (size_t)(b * 5 + oc) * 20736 + sbase;
            #pragma unroll
            for (int p = 0; p < 3; p++) {
                ULL a = acc[oc][p];
                a = add2(a, red[t * 15 + oc * 3 + p]);
                a = add2(a, red[(288 + t) * 15 + oc * 3 + p]);
                const float2 f = unpack2(a);
                float2 o;
                o.x = fmaxf(f.x + bb, 0.0f);
                o.y = fmaxf(f.y + bb, 0.0f);
                *(float2*)(dst + 2 * p) = o;
            }
        }
    }
}

// ---------------------------------------------------------------------------
// conv2: grid = 128 (b); 864 thr = 2 khw-groups x 2 oc-groups x 216 (oh,ow,od)
// Loop ic: SMEM h1 slab 20736 f + w2 padded [10][343][8]=27440 f = 192,704 B
// Reduction pairs khw groups within each oc-group; reuses slab region.
// ---------------------------------------------------------------------------
__global__ __launch_bounds__(864, 1)
void conv2_kernel(const float* __restrict__ w2,
                  const float* __restrict__ b2) {
    extern __shared__ float sm[];
    float* sx = sm;           // 20736 floats (reused as reduction scratch)
    float* sw = sm + 20736;   // 27440 floats (8-padded weights, all 10 oc)

    const int b   = blockIdx.x;
    const int tid = threadIdx.x;
    const int g   = tid / 432;            // khw group 0,1
    const int t2  = tid - g * 432;
    const int ocg = t2 / 216;             // oc-group 0,1 -> oc base 0/5
    const int t   = t2 - ocg * 216;
    const int oh  = t / 36;
    const int ow  = (t % 36) / 6;
    const int od  = t % 6;
    const int ocb = ocg * 5;

    ULL acc[5][3];
    #pragma unroll
    for (int oc = 0; oc < 5; oc++)
        #pragma unroll
        for (int p = 0; p < 3; p++) acc[oc][p] = 0ULL;

    const int k0 = g ? 25 : 0;
    const int k1 = g ? 49 : 25;

    for (int ic = 0; ic < 5; ic++) {
        __syncthreads();   // protect previous iteration's SMEM reads
        {
            const float4* s4 = (const float4*)(g_h1 + (size_t)(b * 5 + ic) * 20736);
            float4* d4 = (float4*)sx;
            for (int i = tid; i < 5184; i += 864) d4[i] = s4[i];
            for (int i = tid; i < 24010; i += 864) {
                const int oc = i / 2401;
                const int r  = i - oc * 2401;
                const int ki = r / 7;
                const int kt = r - ki * 7;
                sw[(oc * 343 + ki) * 8 + kt] = w2[(size_t)(oc * 5 + ic) * 2401 + r];
            }
        }
        __syncthreads();

        #pragma unroll 1
        for (int khw = k0; khw < k1; khw++) {
            const int kh = khw / 7;
            const int kw = khw - kh * 7;
            const float* rowc = sx + ((oh + kh) * 12 + ow + kw) * 144 + od * 12;
            #pragma unroll 1
            for (int kd = 0; kd < 7; kd++) {
                const float* row = rowc + kd * 12;
                float2 v0 = *(const float2*)(row + 0);
                float2 v1 = *(const float2*)(row + 2);
                float2 v2 = *(const float2*)(row + 4);
                float2 v3 = *(const float2*)(row + 6);
                float2 v4 = *(const float2*)(row + 8);
                float2 v5 = *(const float2*)(row + 10);
                ULL xp[11];
                xp[0]  = pack2(v0.x, v0.y);
                xp[2]  = pack2(v1.x, v1.y);
                xp[4]  = pack2(v2.x, v2.y);
                xp[6]  = pack2(v3.x, v3.y);
                xp[8]  = pack2(v4.x, v4.y);
                xp[10] = pack2(v5.x, v5.y);
                xp[1]  = pack2(v0.y, v1.x);
                xp[3]  = pack2(v1.y, v2.x);
                xp[5]  = pack2(v2.y, v3.x);
                xp[7]  = pack2(v3.y, v4.x);
                xp[9]  = pack2(v4.y, v5.x);

                const int kib = khw * 7 + kd;
                #pragma unroll
                for (int oc = 0; oc < 5; oc++) {
                    const float* wb = sw + ((ocb + oc) * 343 + kib) * 8;
                    const float2 wA = *(const float2*)(wb + 0);
                    const float2 wB = *(const float2*)(wb + 2);
                    const float2 wC = *(const float2*)(wb + 4);
                    const float2 wD = *(const float2*)(wb + 6);
                    const float wk[7] = {wA.x, wA.y, wB.x, wB.y, wC.x, wC.y, wD.x};
                    #pragma unroll
                    for (int kt = 0; kt < 7; kt++) {
                        const ULL wp = pack2(wk[kt], wk[kt]);
                        acc[oc][0] = fma2(xp[kt + 0], wp, acc[oc][0]);
                        acc[oc][1] = fma2(xp[kt + 2], wp, acc[oc][1]);
                        acc[oc][2] = fma2(xp[kt + 4], wp, acc[oc][2]);
                    }
                }
            }
        }
    }

    // khw reduction through SMEM (g=1 writes 432*15 ULL = 51,840B into slab region)
    __syncthreads();
    ULL* red = (ULL*)sm;
    if (g == 1) {
        #pragma unroll
        for (int oc = 0; oc < 5; oc++)
            #pragma unroll
            for (int p = 0; p < 3; p++)
                red[(ocg * 216 + t) * 15 + oc * 3 + p] = acc[oc][p];
    }
    __syncthreads();

    if (g == 0) {
        const int sp = oh * 216 + ow * 36 + od * 6;
        #pragma unroll
        for (int oc = 0; oc < 5; oc++) {
            const float bb = __ldg(b2 + ocb + oc);
            float* dst = g_h2 + (size_t)(b * 10 + ocb + oc) * 1296 + sp;
            #pragma unroll
            for (int p = 0; p < 3; p++) {
                const ULL a = add2(acc[oc][p], red[(ocg * 216 + t) * 15 + oc * 3 + p]);
                const float2 f = unpack2(a);
                float2 o;
                o.x = fmaxf(f.x + bb, 0.0f);
                o.y = fmaxf(f.y + bb, 0.0f);
                *(float2*)(dst + 2 * p) = o;
            }
        }
    }
}

// ---------------------------------------------------------------------------
// head: Linear(12960 -> 1) + sigmoid. grid = 128 (b), 128 threads.
// ---------------------------------------------------------------------------
__global__ __launch_bounds__(128, 8)
void head_kernel(const float* __restrict__ wl,
                 const float* __restrict__ bl,
                 float* __restrict__ out) {
    const int b   = blockIdx.x;
    const int tid = threadIdx.x;
    const float* h = g_h2 + (size_t)b * 12960;

    float sum = 0.0f;
    for (int i = tid; i < 12960; i += 128)
        sum += h[i] * wl[i];

    #pragma unroll
    for (int o = 16; o > 0; o >>= 1)
        sum += __shfl_xor_sync(0xffffffffu, sum, o);

    __shared__ float red[4];
    if ((tid & 31) == 0) red[tid >> 5] = sum;
    __syncthreads();
    if (tid == 0) {
        float z = red[0] + red[1] + red[2] + red[3] + bl[0];
        out[b] = 1.0f / (1.0f + expf(-z));
    }
}

// ---------------------------------------------------------------------------
extern "C" void kernel_launch(void* const* d_in, const int* in_sizes, int n_in,
                              void* d_out, int out_size) {
    const float* x  = (const float*)d_in[0];
    const float* w1 = (const float*)d_in[1];
    const float* b1 = (const float*)d_in[2];
    const float* w2 = (const float*)d_in[3];
    const float* b2 = (const float*)d_in[4];
    const float* wl = (const float*)d_in[5];
    const float* bl = (const float*)d_in[6];

    const int smem1 = 54544 * 4;  // 218,176 B
    const int smem2 = 48176 * 4;  // 192,704 B
    cudaFuncSetAttribute(conv1_kernel, cudaFuncAttributeMaxDynamicSharedMemorySize, smem1);
    cudaFuncSetAttribute(conv2_kernel, cudaFuncAttributeMaxDynamicSharedMemorySize, smem2);

    conv1_kernel<<<128 * 12, 864, smem1>>>(x, w1, b1);
    conv2_kernel<<<128, 864, smem2>>>(w2, b2);
    head_kernel<<<128, 128>>>(wl, bl, (float*)d_out);
}